// round 8
// baseline (speedup 1.0000x reference)
#include <cuda_runtime.h>
#include <cuda_bf16.h>

#define NT 1024   // tokens
#define NE 8      // experts
#define NH 1024   // hidden
#define NI 2816   // intermediate
#define TOPK 2

#define BM 128
#define BN 128
#define BK 32
#define SW 20     // smem row stride in uint32 pairs (16 data + 4 pad) -> conflict-free frag loads

// ---------------- scratch (device globals; no allocations allowed) ----------------
__device__ int   g_count[NE];
__device__ int   g_base [NE];
__device__ int   g_tok  [NE * NT];
__device__ int   g_slot [NE * NT];
__device__ float g_gate [NE * NT];
__device__ __align__(16) float g_h1[TOPK * NT * NI];  // h1, later act (in-place)
__device__ __align__(16) float g_h3[TOPK * NT * NI];
__device__ __align__(16) float g_y [TOPK * NT * NH];  // per-(token,slot) outputs

// ---------------- routing: top-2 softmax gates + per-expert compaction ----------------
__global__ void route_kernel(const float* __restrict__ logits) {
    int t = threadIdx.x;            // one thread per token, single block of 1024
    if (t < NE) g_count[t] = 0;
    __syncthreads();

    float l[NE];
#pragma unroll
    for (int e = 0; e < NE; e++) l[e] = logits[t * NE + e];

    int e0 = 0; float v0 = l[0];
#pragma unroll
    for (int e = 1; e < NE; e++) if (l[e] > v0) { v0 = l[e]; e0 = e; }
    int e1 = 0; float v1 = -3.4e38f;
#pragma unroll
    for (int e = 0; e < NE; e++) if (e != e0 && l[e] > v1) { v1 = l[e]; e1 = e; }

    // renormalized top-2 softmax: g0 = e^{v0}/(e^{v0}+e^{v1})
    float p1 = expf(v1 - v0);
    float inv = 1.0f / (1.0f + p1);
    float g0 = inv;
    float g1 = p1 * inv;

    int p;
    p = atomicAdd(&g_count[e0], 1);
    g_tok[e0 * NT + p] = t; g_slot[e0 * NT + p] = 0; g_gate[e0 * NT + p] = g0;
    p = atomicAdd(&g_count[e1], 1);
    g_tok[e1 * NT + p] = t; g_slot[e1 * NT + p] = 1; g_gate[e1 * NT + p] = g1;

    __syncthreads();
    if (t == 0) {
        int acc = 0;
#pragma unroll
        for (int e = 0; e < NE; e++) { g_base[e] = acc; acc += g_count[e]; }
    }
}

// ---------------- helpers ----------------
__device__ __forceinline__ unsigned bfpair(__nv_bfloat16 a, __nv_bfloat16 b) {
    unsigned short ua = *reinterpret_cast<unsigned short*>(&a);
    unsigned short ub = *reinterpret_cast<unsigned short*>(&b);
    return (unsigned)ua | ((unsigned)ub << 16);
}

// split fp32x4 -> (hi bf16x4, lo bf16x4) and store both pairs (8B each)
__device__ __forceinline__ void split_store(unsigned* shi, unsigned* slo, float4 f) {
    __nv_bfloat16 hx = __float2bfloat16(f.x), hy = __float2bfloat16(f.y);
    __nv_bfloat16 hz = __float2bfloat16(f.z), hw = __float2bfloat16(f.w);
    float rx = f.x - __bfloat162float(hx), ry = f.y - __bfloat162float(hy);
    float rz = f.z - __bfloat162float(hz), rw = f.w - __bfloat162float(hw);
    uint2 H = make_uint2(bfpair(hx, hy), bfpair(hz, hw));
    uint2 L = make_uint2(bfpair(__float2bfloat16(rx), __float2bfloat16(ry)),
                         bfpair(__float2bfloat16(rz), __float2bfloat16(rw)));
    *reinterpret_cast<uint2*>(shi) = H;
    *reinterpret_cast<uint2*>(slo) = L;
}

__device__ __forceinline__ void mma_bf16(float c[4], const unsigned a[4], unsigned b0, unsigned b1) {
    asm volatile(
        "mma.sync.aligned.m16n8k16.row.col.f32.bf16.bf16.f32 "
        "{%0,%1,%2,%3}, {%4,%5,%6,%7}, {%8,%9}, {%0,%1,%2,%3};\n"
        : "+f"(c[0]), "+f"(c[1]), "+f"(c[2]), "+f"(c[3])
        : "r"(a[0]), "r"(a[1]), "r"(a[2]), "r"(a[3]), "r"(b0), "r"(b1));
}

// ---------------- grouped GEMM, bf16x3 emulated fp32: C = A @ W^T ----------------
// PHASE1: A = x rows gathered via token list; blockIdx.z = e*2+which (which: 0->w1/h1, 1->w3/h3)
// PHASE2: A = act rows (contiguous per expert); epilogue gate-scales and scatters to g_y
template<int KLEN, int NR, bool PHASE1>
__global__ void __launch_bounds__(256, 1)
moe_gemm(const float* __restrict__ Aglob, const float* __restrict__ W0, const float* __restrict__ W1) {
    int e, which;
    const float* W;
    if (PHASE1) { e = blockIdx.z >> 1; which = blockIdx.z & 1; W = which ? W1 : W0; }
    else        { e = blockIdx.z; which = 0; W = W0; }

    const int count = g_count[e];
    const int mt = blockIdx.y;
    if (mt * BM >= count) return;
    const int nt = blockIdx.x;
    const int base = g_base[e];
    const float* A = PHASE1 ? Aglob : g_h1;   // phase2 reads activations

    __shared__ __align__(16) unsigned sA[2][BM * SW];   // [hi/lo][row][pair]
    __shared__ __align__(16) unsigned sB[2][BN * SW];

    const int tid = threadIdx.x;
    const int c4  = tid & 7;     // float4 column within BK
    const int rt  = tid >> 3;    // 0..31

    const float* aPtr[4];
    const float* bPtr[4];
#pragma unroll
    for (int i = 0; i < 4; i++) {
        int r  = rt + 32 * i;
        int m  = mt * BM + r;
        int mc = m < count ? m : count - 1;     // clamp padded rows (in-bounds, output masked)
        size_t arow = PHASE1 ? (size_t)g_tok[e * NT + mc] : (size_t)(base + mc);
        aPtr[i] = A + arow * (size_t)KLEN + c4 * 4;
        int n  = nt * BN + r;
        bPtr[i] = W + ((size_t)e * NR + n) * (size_t)KLEN + c4 * 4;
    }

    const int wid = tid >> 5, lane = tid & 31;
    const int wm = wid & 1;        // 2 m-warps (64 rows each)
    const int wn = wid >> 1;       // 4 n-warps (32 cols each)
    const int g  = lane >> 2, t4 = lane & 3;

    float acc[4][4][4];
#pragma unroll
    for (int a = 0; a < 4; a++)
#pragma unroll
        for (int b = 0; b < 4; b++)
#pragma unroll
            for (int c = 0; c < 4; c++) acc[a][b][c] = 0.f;

    float4 aR[4], bR[4];
#pragma unroll
    for (int i = 0; i < 4; i++) {
        aR[i] = *(const float4*)aPtr[i];
        bR[i] = *(const float4*)bPtr[i];
    }

    const int KITERS = KLEN / BK;
#pragma unroll 1
    for (int k = 0; k < KITERS; k++) {
        // stage current chunk into hi/lo bf16 smem
#pragma unroll
        for (int i = 0; i < 4; i++) {
            int idx = (rt + 32 * i) * SW + c4 * 2;
            split_store(&sA[0][idx], &sA[1][idx], aR[i]);
            split_store(&sB[0][idx], &sB[1][idx], bR[i]);
        }
        __syncthreads();

        // prefetch next chunk (overlaps with tensor compute below)
        if (k + 1 < KITERS) {
#pragma unroll
            for (int i = 0; i < 4; i++) {
                aR[i] = *(const float4*)(aPtr[i] + (size_t)(k + 1) * BK);
                bR[i] = *(const float4*)(bPtr[i] + (size_t)(k + 1) * BK);
            }
        }

#pragma unroll
        for (int kk = 0; kk < 2; kk++) {            // two k16 steps per BK=32
            const int cp = kk * 8 + t4;
            unsigned ah[4][4], al[4][4];
#pragma unroll
            for (int mi = 0; mi < 4; mi++) {
                int r  = wm * 64 + mi * 16 + g;
                int i0 = r * SW + cp, i1 = (r + 8) * SW + cp;
                ah[mi][0] = sA[0][i0]; ah[mi][1] = sA[0][i1];
                ah[mi][2] = sA[0][i0 + 4]; ah[mi][3] = sA[0][i1 + 4];
                al[mi][0] = sA[1][i0]; al[mi][1] = sA[1][i1];
                al[mi][2] = sA[1][i0 + 4]; al[mi][3] = sA[1][i1 + 4];
            }
#pragma unroll
            for (int ni = 0; ni < 4; ni++) {
                int n  = wn * 32 + ni * 8 + g;
                int ib = n * SW + cp;
                unsigned bh0 = sB[0][ib], bh1 = sB[0][ib + 4];
                unsigned bl0 = sB[1][ib], bl1 = sB[1][ib + 4];
#pragma unroll
                for (int mi = 0; mi < 4; mi++) {
                    mma_bf16(acc[mi][ni], ah[mi], bh0, bh1);   // hi*hi
                    mma_bf16(acc[mi][ni], al[mi], bh0, bh1);   // lo*hi
                    mma_bf16(acc[mi][ni], ah[mi], bl0, bl1);   // hi*lo
                }
            }
        }
        __syncthreads();
    }

    // ---------------- epilogue ----------------
#pragma unroll
    for (int mi = 0; mi < 4; mi++) {
#pragma unroll
        for (int h = 0; h < 2; h++) {
            int row = wm * 64 + mi * 16 + g + h * 8;
            int m = mt * BM + row;
            if (m < count) {
                if (PHASE1) {
                    float* outp = (which ? g_h3 : g_h1) + (size_t)(base + m) * NI + nt * BN;
#pragma unroll
                    for (int ni = 0; ni < 4; ni++) {
                        int col = wn * 32 + ni * 8 + t4 * 2;
                        float2 v = make_float2(acc[mi][ni][h * 2 + 0], acc[mi][ni][h * 2 + 1]);
                        *reinterpret_cast<float2*>(outp + col) = v;
                    }
                } else {
                    int ep = e * NT + m;
                    int tok = g_tok[ep], sl = g_slot[ep];
                    float gate = g_gate[ep];
                    float* outp = g_y + (size_t)(tok * TOPK + sl) * NH + nt * BN;
#pragma unroll
                    for (int ni = 0; ni < 4; ni++) {
                        int col = wn * 32 + ni * 8 + t4 * 2;
                        float2 v = make_float2(acc[mi][ni][h * 2 + 0] * gate,
                                               acc[mi][ni][h * 2 + 1] * gate);
                        *reinterpret_cast<float2*>(outp + col) = v;
                    }
                }
            }
        }
    }
}

// ---------------- act = silu(h1) * h3 (in place into g_h1) ----------------
__global__ void act_kernel() {
    size_t i = (size_t)blockIdx.x * 256 + threadIdx.x;   // float4 index
    float4 a = reinterpret_cast<const float4*>(g_h1)[i];
    float4 b = reinterpret_cast<const float4*>(g_h3)[i];
    a.x = a.x / (1.0f + expf(-a.x)) * b.x;
    a.y = a.y / (1.0f + expf(-a.y)) * b.y;
    a.z = a.z / (1.0f + expf(-a.z)) * b.z;
    a.w = a.w / (1.0f + expf(-a.w)) * b.w;
    reinterpret_cast<float4*>(g_h1)[i] = a;
}

// ---------------- out[t] = y[t,slot0] + y[t,slot1] ----------------
__global__ void combine_kernel(float* __restrict__ out) {
    int i = blockIdx.x * 256 + threadIdx.x;   // float4 index over [1024,1024]
    int t = i >> 8;                            // 256 float4 per row
    int h = i & 255;
    const float4* y = reinterpret_cast<const float4*>(g_y);
    float4 a = y[(size_t)(2 * t) * 256 + h];
    float4 b = y[(size_t)(2 * t + 1) * 256 + h];
    float4 o = make_float4(a.x + b.x, a.y + b.y, a.z + b.z, a.w + b.w);
    reinterpret_cast<float4*>(out)[i] = o;
}

// ---------------- launch ----------------
extern "C" void kernel_launch(void* const* d_in, const int* in_sizes, int n_in,
                              void* d_out, int out_size) {
    const float* x  = (const float*)d_in[0];   // [1024, 1024]
    const float* rl = (const float*)d_in[1];   // [1024, 8]
    const float* w1 = (const float*)d_in[2];   // [8, 2816, 1024]
    const float* w3 = (const float*)d_in[3];   // [8, 2816, 1024]
    const float* w2 = (const float*)d_in[4];   // [8, 1024, 2816]
    float* out = (float*)d_out;                // [1024, 1024]

    route_kernel<<<1, 1024>>>(rl);

    // GEMM1: h1/h3 = x @ w{1,3}^T per expert; z = e*2 + which
    dim3 g1(NI / BN, NT / BM, NE * 2);   // (22, 8, 16)
    moe_gemm<NH, NI, true><<<g1, 256>>>(x, w1, w3);

    act_kernel<<<(TOPK * NT * NI) / (4 * 256), 256>>>();   // 5632 blocks

    // GEMM2: y = act @ w2^T, gate-scaled, scattered per (token, slot)
    dim3 g2(NH / BN, NT / BM, NE);       // (8, 8, 8)
    moe_gemm<NI, NH, false><<<g2, 256>>>(x, w2, w2);

    combine_kernel<<<(NT * NH) / (4 * 256), 256>>>(out);   // 1024 blocks
}